// round 6
// baseline (speedup 1.0000x reference)
#include <cuda_runtime.h>
#include <math.h>

#define NMAX   50000
#define EMAX   1600000
#define CCH    128
#define EPS_BN 1e-5f
#define NBG    ((NMAX + 31) / 32)        // fused-GRU blocks (32 rows each)

static inline int ceildiv(int a, int b) { return (a + b - 1) / b; }

// ---------------------------------------------------------------------------
// Device scratch: ONE pool + CSR + small stats.  Total ≈ 118 MB.
// Pool layout (floats):
//   [0 .. N*256)        xin  (dead after merge GEMM)
//   [0 .. N*128)        hc   (aliases xin; written only after xin is dead)
//   [N*256 .. N*384)    x    (merged features)
//   [N*384 .. N*512)    sk   (skip branch, alive until gate2)
// Pre-gather features h live in d_out's H2 half (dead until gate2).
// ---------------------------------------------------------------------------
#define OFF_XIN 0
#define OFF_HC  0
#define OFF_X   ((size_t)NMAX * 256)
#define OFF_SK  ((size_t)NMAX * 384)

__device__ __align__(16) float g_pool[(size_t)NMAX * 512];
__device__ float g_dinv[NMAX];
__device__ int   g_deg[NMAX];
__device__ int   g_cursor[NMAX];
__device__ int   g_rowptr[NMAX + 1];
__device__ int   g_csrc[EMAX];
__device__ float g_ccoef[EMAX];
__device__ float g_ps1[(size_t)NBG * CCH];
__device__ float g_ps2[(size_t)NBG * CCH];
__device__ float g_mean[CCH];
__device__ float g_scale[CCH];

// ---------------------------------------------------------------------------
// Generic SGEMM body: C[M x 128] = A[M x K] @ B[128 x K]^T (+bias)
// BM=128, BN=128, BK=16, TM=TN=8, 256 threads.
// ---------------------------------------------------------------------------
#define BM 128
#define BK 16
#define SP 132   // padded smem row stride

__device__ __forceinline__
void sgemm_body(const float* __restrict__ A, const float* __restrict__ B,
                const float* __restrict__ bias, float* __restrict__ C,
                int M, int K) {
    __shared__ float As[BK * SP];
    __shared__ float Bs[BK * SP];

    const int bm = blockIdx.x * BM;
    const int tid = threadIdx.x;
    const int tx = tid & 15;
    const int ty = tid >> 4;

    float acc[8][8];
    #pragma unroll
    for (int i = 0; i < 8; i++)
        #pragma unroll
        for (int j = 0; j < 8; j++) acc[i][j] = 0.f;

    for (int k0 = 0; k0 < K; k0 += BK) {
        #pragma unroll
        for (int i = 0; i < 8; i++) {
            int idx = tid + i * 256;        // 0..2047
            int k = idx & 15;
            int r = idx >> 4;
            int grow = bm + r;
            float v = (grow < M) ? A[(size_t)grow * K + k0 + k] : 0.f;
            As[k * SP + r] = v;
        }
        #pragma unroll
        for (int i = 0; i < 8; i++) {
            int idx = tid + i * 256;
            int k = idx & 15;
            int c = idx >> 4;
            Bs[k * SP + c] = B[(size_t)c * K + k0 + k];
        }
        __syncthreads();

        #pragma unroll
        for (int k = 0; k < BK; k++) {
            float ra[8], rb[8];
            #pragma unroll
            for (int i = 0; i < 8; i++) ra[i] = As[k * SP + ty * 8 + i];
            #pragma unroll
            for (int j = 0; j < 8; j++) rb[j] = Bs[k * SP + tx * 8 + j];
            #pragma unroll
            for (int i = 0; i < 8; i++)
                #pragma unroll
                for (int j = 0; j < 8; j++)
                    acc[i][j] = fmaf(ra[i], rb[j], acc[i][j]);
        }
        __syncthreads();
    }

    #pragma unroll
    for (int i = 0; i < 8; i++) {
        int grow = bm + ty * 8 + i;
        if (grow >= M) break;
        #pragma unroll
        for (int j = 0; j < 8; j++) {
            int gcol = tx * 8 + j;
            float v = acc[i][j];
            if (bias) v += bias[gcol];
            C[(size_t)grow * CCH + gcol] = v;
        }
    }
}

// GEMM wrappers — scratch bound by symbol inside device code
__global__ __launch_bounds__(256, 2)
void gemm_merge(const float* __restrict__ W, const float* __restrict__ b, int M) {
    sgemm_body(g_pool + OFF_XIN, W, b, g_pool + OFF_X, M, 256);
}
__global__ __launch_bounds__(256, 2)
void gemm_skip(const float* __restrict__ W, const float* __restrict__ b, int M) {
    sgemm_body(g_pool + OFF_X, W, b, g_pool + OFF_SK, M, 128);
}
__global__ __launch_bounds__(256, 2)
void gemm_w1(const float* __restrict__ W, float* __restrict__ h, int M) {
    sgemm_body(g_pool + OFF_X, W, nullptr, h, M, 128);
}
__global__ __launch_bounds__(256, 2)
void gemm_w2(const float* __restrict__ H1, const float* __restrict__ W,
             float* __restrict__ h, int M) {
    sgemm_body(H1, W, nullptr, h, M, 128);
}

// ---------------------------------------------------------------------------
// Fused GRU GEMM+gate: block = 32 rows x 384 cols, BOTH gi=hc@Wih^T and
// gh=xprev@Whh^T, gate combine in epilogue.  512 threads, BK=8.
// LAYER 1: out = relu(gru)               -> H1
// LAYER 2: out = gru + sk, + BN partials -> H2
// ---------------------------------------------------------------------------
#define GBK 8
#define BPad 385
#define APad 33

template<int LAYER>
__global__ __launch_bounds__(512, 1)
void gru_fused(const float* __restrict__ Wih, const float* __restrict__ Whh,
               const float* __restrict__ bih, const float* __restrict__ bhh,
               const float* __restrict__ xprev, float* __restrict__ outH, int n) {
    __shared__ float Bi[GBK * BPad];
    __shared__ float Bh[GBK * BPad];
    __shared__ float Ahc[GBK * APad];
    __shared__ float Axp[GBK * APad];

    const int tid = threadIdx.x;
    const int tx = tid & 63;      // 64 col groups x 2 channels
    const int ty = tid >> 6;      // 8 row groups x 4 rows
    const int bm = blockIdx.x * 32;
    const float* hc = g_pool + OFF_HC;

    float ai[4][3][2], ah[4][3][2];
    #pragma unroll
    for (int i = 0; i < 4; i++)
        #pragma unroll
        for (int g = 0; g < 3; g++)
            #pragma unroll
            for (int q = 0; q < 2; q++) { ai[i][g][q] = 0.f; ah[i][g][q] = 0.f; }

    for (int k0 = 0; k0 < 128; k0 += GBK) {
        #pragma unroll
        for (int i = 0; i < 6; i++) {
            int idx = tid + i * 512;          // 0..3071
            int c = idx >> 3;
            int k = idx & 7;
            Bi[k * BPad + c] = Wih[(size_t)c * 128 + k0 + k];
            Bh[k * BPad + c] = Whh[(size_t)c * 128 + k0 + k];
        }
        {
            int matsel = tid >> 8;            // 0: hc, 1: xprev
            int rem = tid & 255;
            int r = rem >> 3;
            int k = rem & 7;
            int grow = bm + r;
            const float* src = matsel ? xprev : hc;
            float v = (grow < n) ? src[(size_t)grow * 128 + k0 + k] : 0.f;
            if (matsel) Axp[k * APad + r] = v;
            else        Ahc[k * APad + r] = v;
        }
        __syncthreads();

        #pragma unroll
        for (int k = 0; k < GBK; k++) {
            float rhc[4], rxp[4];
            #pragma unroll
            for (int i = 0; i < 4; i++) {
                rhc[i] = Ahc[k * APad + ty * 4 + i];
                rxp[i] = Axp[k * APad + ty * 4 + i];
            }
            float wi[3][2], wh[3][2];
            #pragma unroll
            for (int g = 0; g < 3; g++) {
                int cb = g * 128 + tx * 2;
                wi[g][0] = Bi[k * BPad + cb];     wi[g][1] = Bi[k * BPad + cb + 1];
                wh[g][0] = Bh[k * BPad + cb];     wh[g][1] = Bh[k * BPad + cb + 1];
            }
            #pragma unroll
            for (int i = 0; i < 4; i++)
                #pragma unroll
                for (int g = 0; g < 3; g++)
                    #pragma unroll
                    for (int q = 0; q < 2; q++) {
                        ai[i][g][q] = fmaf(rhc[i], wi[g][q], ai[i][g][q]);
                        ah[i][g][q] = fmaf(rxp[i], wh[g][q], ah[i][g][q]);
                    }
        }
        __syncthreads();
    }

    float bi_[3][2], bh_[3][2];
    #pragma unroll
    for (int g = 0; g < 3; g++)
        #pragma unroll
        for (int q = 0; q < 2; q++) {
            bi_[g][q] = bih[g * 128 + tx * 2 + q];
            bh_[g][q] = bhh[g * 128 + tx * 2 + q];
        }

    float ls[2], ls2[2];
    ls[0] = ls[1] = ls2[0] = ls2[1] = 0.f;

    #pragma unroll
    for (int i = 0; i < 4; i++) {
        int row = bm + ty * 4 + i;
        if (row >= n) break;
        #pragma unroll
        for (int q = 0; q < 2; q++) {
            int c = tx * 2 + q;
            float gr = (ai[i][0][q] + bi_[0][q]) + (ah[i][0][q] + bh_[0][q]);
            float gz = (ai[i][1][q] + bi_[1][q]) + (ah[i][1][q] + bh_[1][q]);
            float r = 1.f / (1.f + expf(-gr));
            float z = 1.f / (1.f + expf(-gz));
            float nn = tanhf((ai[i][2][q] + bi_[2][q]) + r * (ah[i][2][q] + bh_[2][q]));
            float hprev = xprev[(size_t)row * 128 + c];
            float val = (1.f - z) * nn + z * hprev;
            if (LAYER == 1) {
                outH[(size_t)row * 128 + c] = fmaxf(val, 0.f);
            } else {
                val += g_pool[OFF_SK + (size_t)row * 128 + c];
                outH[(size_t)row * 128 + c] = val;
                ls[q] += val;
                ls2[q] += val * val;
            }
        }
    }

    if (LAYER == 2) {
        __syncthreads();
        float* red = Bi;
        red[(tx * 2 + 0) * 8 + ty] = ls[0];
        red[(tx * 2 + 1) * 8 + ty] = ls[1];
        float* red2 = Bh;
        red2[(tx * 2 + 0) * 8 + ty] = ls2[0];
        red2[(tx * 2 + 1) * 8 + ty] = ls2[1];
        __syncthreads();
        if (tid < 128) {
            float s = 0.f, s2 = 0.f;
            #pragma unroll
            for (int t = 0; t < 8; t++) { s += red[tid * 8 + t]; s2 += red2[tid * 8 + t]; }
            g_ps1[(size_t)blockIdx.x * CCH + tid] = s;
            g_ps2[(size_t)blockIdx.x * CCH + tid] = s2;
        }
    }
}

// ---------------------------------------------------------------------------
// CSR build — edge_index is INT32 (harness dtype), int atomics only
// ---------------------------------------------------------------------------
__global__ void k_zero(int n) {
    int i = blockIdx.x * blockDim.x + threadIdx.x;
    if (i < n) { g_deg[i] = 0; g_cursor[i] = 0; }
}
__global__ void k_count(const int* __restrict__ ei, int e) {
    int i = blockIdx.x * blockDim.x + threadIdx.x;
    if (i < e) atomicAdd(&g_deg[ei[e + i]], 1);
}
__global__ void k_dinv(int n) {
    int i = blockIdx.x * blockDim.x + threadIdx.x;
    if (i < n) g_dinv[i] = rsqrtf((float)(g_deg[i] + 1));
}
__global__ void k_scan(int n) {
    __shared__ int ssum[1024];
    int tid = threadIdx.x;
    int chunk = (n + 1023) / 1024;
    int beg = tid * chunk; if (beg > n) beg = n;
    int end = beg + chunk; if (end > n) end = n;
    int s = 0;
    for (int i = beg; i < end; i++) s += g_deg[i];
    ssum[tid] = s;
    __syncthreads();
    if (tid == 0) {
        int acc = 0;
        for (int i = 0; i < 1024; i++) { int v = ssum[i]; ssum[i] = acc; acc += v; }
        g_rowptr[n] = acc;
    }
    __syncthreads();
    int acc = ssum[tid];
    for (int i = beg; i < end; i++) { g_rowptr[i] = acc; acc += g_deg[i]; }
}
__global__ void k_place(const int* __restrict__ ei, int e) {
    int i = blockIdx.x * blockDim.x + threadIdx.x;
    if (i >= e) return;
    int s = ei[i];
    int d = ei[e + i];
    int p = g_rowptr[d] + atomicAdd(&g_cursor[d], 1);
    g_csrc[p] = s;
    g_ccoef[p] = g_dinv[s] * g_dinv[d];
}

// ---------------------------------------------------------------------------
// Gather (warp per node): hc[d] = dinv^2*h[d] + sum coef*h[s] + bias
// ---------------------------------------------------------------------------
__global__ __launch_bounds__(256)
void k_gather(const float* __restrict__ h, const float* __restrict__ bias, int n) {
    int w = (blockIdx.x * blockDim.x + threadIdx.x) >> 5;
    int lane = threadIdx.x & 31;
    if (w >= n) return;
    int beg = g_rowptr[w], end = g_rowptr[w + 1];
    float di = g_dinv[w];
    float4 hv = *(const float4*)(h + (size_t)w * CCH + lane * 4);
    float sl = di * di;
    float ax = sl * hv.x, ay = sl * hv.y, az = sl * hv.z, aw = sl * hv.w;

    int j = beg;
    for (; j + 1 < end; j += 2) {
        int s0 = g_csrc[j], s1 = g_csrc[j + 1];
        float c0 = g_ccoef[j], c1 = g_ccoef[j + 1];
        float4 v0 = *(const float4*)(h + (size_t)s0 * CCH + lane * 4);
        float4 v1 = *(const float4*)(h + (size_t)s1 * CCH + lane * 4);
        ax = fmaf(c0, v0.x, ax); ay = fmaf(c0, v0.y, ay);
        az = fmaf(c0, v0.z, az); aw = fmaf(c0, v0.w, aw);
        ax = fmaf(c1, v1.x, ax); ay = fmaf(c1, v1.y, ay);
        az = fmaf(c1, v1.z, az); aw = fmaf(c1, v1.w, aw);
    }
    if (j < end) {
        int s0 = g_csrc[j];
        float c0 = g_ccoef[j];
        float4 v0 = *(const float4*)(h + (size_t)s0 * CCH + lane * 4);
        ax = fmaf(c0, v0.x, ax); ay = fmaf(c0, v0.y, ay);
        az = fmaf(c0, v0.z, az); aw = fmaf(c0, v0.w, aw);
    }
    float b0 = bias[lane * 4 + 0], b1 = bias[lane * 4 + 1];
    float b2 = bias[lane * 4 + 2], b3 = bias[lane * 4 + 3];
    float4 o; o.x = ax + b0; o.y = ay + b1; o.z = az + b2; o.w = aw + b3;
    *(float4*)(g_pool + OFF_HC + (size_t)w * CCH + lane * 4) = o;
}

// ---------------------------------------------------------------------------
// Elementwise / BN
// ---------------------------------------------------------------------------
__global__ void k_xin(const float* __restrict__ nf, const float* __restrict__ ts,
                      const float* __restrict__ freq, const float* __restrict__ phase,
                      int n) {
    int idx = blockIdx.x * blockDim.x + threadIdx.x;
    if (idx >= n * CCH) return;
    int nn = idx >> 7, c = idx & 127;
    g_pool[OFF_XIN + (size_t)nn * 256 + c] = nf[idx];
    g_pool[OFF_XIN + (size_t)nn * 256 + 128 + c] = cosf(ts[nn] * freq[c] + phase[c]);
}

__global__ void k_bnstats(int nblocks, int n) {
    int c = threadIdx.x;    // 128 threads
    float s = 0.f, comp = 0.f, s2 = 0.f, comp2 = 0.f;
    for (int b = 0; b < nblocks; b++) {
        float y = g_ps1[(size_t)b * CCH + c] - comp;
        float t = s + y; comp = (t - s) - y; s = t;
        float y2 = g_ps2[(size_t)b * CCH + c] - comp2;
        float t2 = s2 + y2; comp2 = (t2 - s2) - y2; s2 = t2;
    }
    float invn = 1.f / (float)n;
    float mean = s * invn;
    float var = s2 * invn - mean * mean;
    g_mean[c] = mean;
    g_scale[c] = rsqrtf(var + EPS_BN);
}

__global__ void k_bnapply(float* __restrict__ out2, int n) {
    int idx = blockIdx.x * blockDim.x + threadIdx.x;
    if (idx >= n * CCH) return;
    int c = idx & 127;
    out2[idx] = (out2[idx] - g_mean[c]) * g_scale[c];
}

// ---------------------------------------------------------------------------
// Launch
// ---------------------------------------------------------------------------
extern "C" void kernel_launch(void* const* d_in, const int* in_sizes, int n_in,
                              void* d_out, int out_size) {
    const float* nf    = (const float*)d_in[0];
    const int*   ei    = (const int*)d_in[1];        // int32! (JAX x64 off)
    const float* xp1   = (const float*)d_in[2];
    const float* xp2   = (const float*)d_in[3];
    const float* ts    = (const float*)d_in[4];
    const float* freq  = (const float*)d_in[5];
    const float* phase = (const float*)d_in[6];
    const float* mW    = (const float*)d_in[7];
    const float* mb    = (const float*)d_in[8];
    const float* W1    = (const float*)d_in[9];
    const float* b1    = (const float*)d_in[10];
    const float* g1Wih = (const float*)d_in[11];
    const float* g1Whh = (const float*)d_in[12];
    const float* g1bih = (const float*)d_in[13];
    const float* g1bhh = (const float*)d_in[14];
    const float* W2    = (const float*)d_in[15];
    const float* b2    = (const float*)d_in[16];
    const float* g2Wih = (const float*)d_in[17];
    const float* g2Whh = (const float*)d_in[18];
    const float* g2bih = (const float*)d_in[19];
    const float* g2bhh = (const float*)d_in[20];
    const float* skW   = (const float*)d_in[21];
    const float* skb   = (const float*)d_in[22];

    float* out = (float*)d_out;

    const int n = in_sizes[0] / CCH;     // 50000
    const int e = in_sizes[1] / 2;       // 1600000
    const int nc = n * CCH;

    float* H1 = out;
    float* H2 = out + nc;                // also used as pre-gather scratch

    const int T = 256;
    dim3 gN(ceildiv(n, T));
    dim3 gE(ceildiv(e, T));
    dim3 gNC(ceildiv(nc, T));
    dim3 gGat(ceildiv(n * 32, T));
    dim3 gM(ceildiv(n, BM));
    int nbg = ceildiv(n, 32);

    // CSR build
    k_zero <<<gN, T>>>(n);
    k_count<<<gE, T>>>(ei, e);
    k_dinv <<<gN, T>>>(n);
    k_scan <<<1, 1024>>>(n);
    k_place<<<gE, T>>>(ei, e);

    // time encode + merge + skip
    k_xin<<<gNC, T>>>(nf, ts, freq, phase, n);
    gemm_merge<<<gM, 256>>>(mW, mb, n);
    gemm_skip <<<gM, 256>>>(skW, skb, n);

    // ---- layer 1 ----
    gemm_w1<<<gM, 256>>>(W1, H2, n);            // h -> H2 scratch
    k_gather<<<gGat, T>>>(H2, b1, n);           // hc -> pool
    gru_fused<1><<<nbg, 512>>>(g1Wih, g1Whh, g1bih, g1bhh, xp1, H1, n);

    // ---- layer 2 ----
    gemm_w2<<<gM, 256>>>(H1, W2, H2, n);        // h -> H2 scratch
    k_gather<<<gGat, T>>>(H2, b2, n);
    gru_fused<2><<<nbg, 512>>>(g2Wih, g2Whh, g2bih, g2bhh, xp2, H2, n);

    // batchnorm
    k_bnstats<<<1, 128>>>(nbg, n);
    k_bnapply<<<gNC, T>>>(H2, n);
}

// round 7
// speedup vs baseline: 1.1829x; 1.1829x over previous
#include <cuda_runtime.h>
#include <math.h>

#define NMAX   50000
#define EMAX   1600000
#define CCH    128
#define EPS_BN 1e-5f
#define NBG    ((NMAX + 31) / 32)

static inline int ceildiv(int a, int b) { return (a + b - 1) / b; }

// ---------------------------------------------------------------------------
// Packed f32x2 helpers (FFMA2: 2 fp32 FMAs per instruction, RN per lane)
// ---------------------------------------------------------------------------
__device__ __forceinline__ unsigned long long dup2(float x) {
    unsigned long long r;
    asm("mov.b64 %0, {%1,%1};" : "=l"(r) : "f"(x));
    return r;
}
__device__ __forceinline__ void fma2(unsigned long long& d,
                                     unsigned long long a, unsigned long long b) {
    asm("fma.rn.f32x2 %0, %1, %2, %0;" : "+l"(d) : "l"(a), "l"(b));
}
__device__ __forceinline__ float2 unpk2(unsigned long long v) {
    float2 f;
    asm("mov.b64 {%0,%1}, %2;" : "=f"(f.x), "=f"(f.y) : "l"(v));
    return f;
}

// ---------------------------------------------------------------------------
// Device scratch (≈118 MB pool + CSR + stats)
// ---------------------------------------------------------------------------
#define OFF_XIN 0
#define OFF_HC  0
#define OFF_X   ((size_t)NMAX * 256)
#define OFF_SK  ((size_t)NMAX * 384)

__device__ __align__(16) float g_pool[(size_t)NMAX * 512];
__device__ float g_dinv[NMAX];
__device__ int   g_deg[NMAX];
__device__ int   g_cursor[NMAX];
__device__ int   g_rowptr[NMAX + 1];
__device__ int   g_csrc[EMAX];
__device__ float g_ccoef[EMAX];
__device__ float g_ps1[(size_t)NBG * CCH];
__device__ float g_ps2[(size_t)NBG * CCH];
__device__ float g_mean[CCH];
__device__ float g_scale[CCH];

// ---------------------------------------------------------------------------
// SGEMM body: C[M x 128] = A[M x K] @ B[128 x K]^T (+bias), f32x2 inner loop
// ---------------------------------------------------------------------------
#define BM 128
#define BK 16
#define SP 132

__device__ __forceinline__
void sgemm_body(const float* __restrict__ A, const float* __restrict__ B,
                const float* __restrict__ bias, float* __restrict__ C,
                int M, int K) {
    __shared__ __align__(16) float As[BK * SP];
    __shared__ __align__(16) float Bs[BK * SP];

    const int bm = blockIdx.x * BM;
    const int tid = threadIdx.x;
    const int tx = tid & 15;
    const int ty = tid >> 4;

    unsigned long long acc2[8][4];
    #pragma unroll
    for (int i = 0; i < 8; i++)
        #pragma unroll
        for (int j = 0; j < 4; j++) acc2[i][j] = 0ull;

    for (int k0 = 0; k0 < K; k0 += BK) {
        #pragma unroll
        for (int i = 0; i < 8; i++) {
            int idx = tid + i * 256;
            int k = idx & 15;
            int r = idx >> 4;
            int grow = bm + r;
            float v = (grow < M) ? A[(size_t)grow * K + k0 + k] : 0.f;
            As[k * SP + r] = v;
        }
        #pragma unroll
        for (int i = 0; i < 8; i++) {
            int idx = tid + i * 256;
            int k = idx & 15;
            int c = idx >> 4;
            Bs[k * SP + c] = B[(size_t)c * K + k0 + k];
        }
        __syncthreads();

        #pragma unroll
        for (int k = 0; k < BK; k++) {
            unsigned long long ra2[8], rb2[4];
            #pragma unroll
            for (int i = 0; i < 8; i++) ra2[i] = dup2(As[k * SP + ty * 8 + i]);
            #pragma unroll
            for (int j = 0; j < 4; j++)
                rb2[j] = *(const unsigned long long*)(Bs + k * SP + tx * 8 + j * 2);
            #pragma unroll
            for (int i = 0; i < 8; i++)
                #pragma unroll
                for (int j = 0; j < 4; j++)
                    fma2(acc2[i][j], ra2[i], rb2[j]);
        }
        __syncthreads();
    }

    #pragma unroll
    for (int i = 0; i < 8; i++) {
        int grow = bm + ty * 8 + i;
        if (grow >= M) break;
        #pragma unroll
        for (int j = 0; j < 4; j++) {
            int gcol = tx * 8 + j * 2;
            float2 v = unpk2(acc2[i][j]);
            if (bias) { v.x += bias[gcol]; v.y += bias[gcol + 1]; }
            *(float2*)(C + (size_t)grow * CCH + gcol) = v;
        }
    }
}

__global__ __launch_bounds__(256, 2)
void gemm_merge(const float* __restrict__ W, const float* __restrict__ b, int M) {
    sgemm_body(g_pool + OFF_XIN, W, b, g_pool + OFF_X, M, 256);
}
__global__ __launch_bounds__(256, 2)
void gemm_skip(const float* __restrict__ W, const float* __restrict__ b, int M) {
    sgemm_body(g_pool + OFF_X, W, b, g_pool + OFF_SK, M, 128);
}
__global__ __launch_bounds__(256, 2)
void gemm_w1(const float* __restrict__ W, float* __restrict__ h, int M) {
    sgemm_body(g_pool + OFF_X, W, nullptr, h, M, 128);
}
__global__ __launch_bounds__(256, 2)
void gemm_w2(const float* __restrict__ H1, const float* __restrict__ W,
             float* __restrict__ h, int M) {
    sgemm_body(H1, W, nullptr, h, M, 128);
}

// ---------------------------------------------------------------------------
// Fused GRU GEMM+gate (f32x2): 32 rows x 384 cols, both gi and gh, 512 thr
// ---------------------------------------------------------------------------
#define GBK 8
#define BPad 386      // even -> 8B-aligned pair loads at k*BPad + even col
#define APad 33

template<int LAYER>
__global__ __launch_bounds__(512, 1)
void gru_fused(const float* __restrict__ Wih, const float* __restrict__ Whh,
               const float* __restrict__ bih, const float* __restrict__ bhh,
               const float* __restrict__ xprev, float* __restrict__ outH, int n) {
    __shared__ __align__(16) float Bi[GBK * BPad];
    __shared__ __align__(16) float Bh[GBK * BPad];
    __shared__ __align__(16) float Ahc[GBK * APad];
    __shared__ __align__(16) float Axp[GBK * APad];

    const int tid = threadIdx.x;
    const int tx = tid & 63;
    const int ty = tid >> 6;
    const int bm = blockIdx.x * 32;
    const float* hc = g_pool + OFF_HC;

    unsigned long long ai2[4][3], ah2[4][3];
    #pragma unroll
    for (int i = 0; i < 4; i++)
        #pragma unroll
        for (int g = 0; g < 3; g++) { ai2[i][g] = 0ull; ah2[i][g] = 0ull; }

    for (int k0 = 0; k0 < 128; k0 += GBK) {
        #pragma unroll
        for (int i = 0; i < 6; i++) {
            int idx = tid + i * 512;
            int c = idx >> 3;
            int k = idx & 7;
            Bi[k * BPad + c] = Wih[(size_t)c * 128 + k0 + k];
            Bh[k * BPad + c] = Whh[(size_t)c * 128 + k0 + k];
        }
        {
            int matsel = tid >> 8;
            int rem = tid & 255;
            int r = rem >> 3;
            int k = rem & 7;
            int grow = bm + r;
            const float* src = matsel ? xprev : hc;
            float v = (grow < n) ? src[(size_t)grow * 128 + k0 + k] : 0.f;
            if (matsel) Axp[k * APad + r] = v;
            else        Ahc[k * APad + r] = v;
        }
        __syncthreads();

        #pragma unroll
        for (int k = 0; k < GBK; k++) {
            unsigned long long rhc2[4], rxp2[4], wi2[3], wh2[3];
            #pragma unroll
            for (int i = 0; i < 4; i++) {
                rhc2[i] = dup2(Ahc[k * APad + ty * 4 + i]);
                rxp2[i] = dup2(Axp[k * APad + ty * 4 + i]);
            }
            #pragma unroll
            for (int g = 0; g < 3; g++) {
                int cb = g * 128 + tx * 2;
                wi2[g] = *(const unsigned long long*)(Bi + k * BPad + cb);
                wh2[g] = *(const unsigned long long*)(Bh + k * BPad + cb);
            }
            #pragma unroll
            for (int i = 0; i < 4; i++)
                #pragma unroll
                for (int g = 0; g < 3; g++) {
                    fma2(ai2[i][g], rhc2[i], wi2[g]);
                    fma2(ah2[i][g], rxp2[i], wh2[g]);
                }
        }
        __syncthreads();
    }

    float bi_[3][2], bh_[3][2];
    #pragma unroll
    for (int g = 0; g < 3; g++)
        #pragma unroll
        for (int q = 0; q < 2; q++) {
            bi_[g][q] = bih[g * 128 + tx * 2 + q];
            bh_[g][q] = bhh[g * 128 + tx * 2 + q];
        }

    float ls[2], ls2[2];
    ls[0] = ls[1] = ls2[0] = ls2[1] = 0.f;

    #pragma unroll
    for (int i = 0; i < 4; i++) {
        int row = bm + ty * 4 + i;
        if (row >= n) break;
        float2 aiv[3], ahv[3];
        #pragma unroll
        for (int g = 0; g < 3; g++) { aiv[g] = unpk2(ai2[i][g]); ahv[g] = unpk2(ah2[i][g]); }
        #pragma unroll
        for (int q = 0; q < 2; q++) {
            int c = tx * 2 + q;
            float a0 = q ? aiv[0].y : aiv[0].x, h0 = q ? ahv[0].y : ahv[0].x;
            float a1 = q ? aiv[1].y : aiv[1].x, h1 = q ? ahv[1].y : ahv[1].x;
            float a2 = q ? aiv[2].y : aiv[2].x, h2 = q ? ahv[2].y : ahv[2].x;
            float gr = (a0 + bi_[0][q]) + (h0 + bh_[0][q]);
            float gz = (a1 + bi_[1][q]) + (h1 + bh_[1][q]);
            float r = 1.f / (1.f + expf(-gr));
            float z = 1.f / (1.f + expf(-gz));
            float nn = tanhf((a2 + bi_[2][q]) + r * (h2 + bh_[2][q]));
            float hprev = xprev[(size_t)row * 128 + c];
            float val = (1.f - z) * nn + z * hprev;
            if (LAYER == 1) {
                outH[(size_t)row * 128 + c] = fmaxf(val, 0.f);
            } else {
                val += g_pool[OFF_SK + (size_t)row * 128 + c];
                outH[(size_t)row * 128 + c] = val;
                ls[q] += val;
                ls2[q] += val * val;
            }
        }
    }

    if (LAYER == 2) {
        __syncthreads();
        float* red = Bi;
        red[(tx * 2 + 0) * 8 + ty] = ls[0];
        red[(tx * 2 + 1) * 8 + ty] = ls[1];
        float* red2 = Bh;
        red2[(tx * 2 + 0) * 8 + ty] = ls2[0];
        red2[(tx * 2 + 1) * 8 + ty] = ls2[1];
        __syncthreads();
        if (tid < 128) {
            float s = 0.f, s2 = 0.f;
            #pragma unroll
            for (int t = 0; t < 8; t++) { s += red[tid * 8 + t]; s2 += red2[tid * 8 + t]; }
            g_ps1[(size_t)blockIdx.x * CCH + tid] = s;
            g_ps2[(size_t)blockIdx.x * CCH + tid] = s2;
        }
    }
}

// ---------------------------------------------------------------------------
// CSR build — edge_index is INT32
// ---------------------------------------------------------------------------
__global__ void k_zero(int n) {
    int i = blockIdx.x * blockDim.x + threadIdx.x;
    if (i < n) { g_deg[i] = 0; g_cursor[i] = 0; }
}
__global__ void k_count(const int* __restrict__ ei, int e) {
    int i = blockIdx.x * blockDim.x + threadIdx.x;
    if (i < e) atomicAdd(&g_deg[ei[e + i]], 1);
}
__global__ void k_dinv(int n) {
    int i = blockIdx.x * blockDim.x + threadIdx.x;
    if (i < n) g_dinv[i] = rsqrtf((float)(g_deg[i] + 1));
}

// exclusive scan via warp shuffles (1 block, 1024 threads)
__global__ void k_scan(int n) {
    __shared__ int wsum[32];
    int tid = threadIdx.x;
    int lane = tid & 31, wid = tid >> 5;
    int chunk = (n + 1023) / 1024;
    int beg = tid * chunk; if (beg > n) beg = n;
    int end = beg + chunk; if (end > n) end = n;
    int s = 0;
    for (int i = beg; i < end; i++) s += g_deg[i];
    int v = s;
    #pragma unroll
    for (int o = 1; o < 32; o <<= 1) {
        int t = __shfl_up_sync(0xffffffffu, v, o);
        if (lane >= o) v += t;
    }
    if (lane == 31) wsum[wid] = v;
    __syncthreads();
    if (wid == 0) {
        int w = wsum[lane];
        #pragma unroll
        for (int o = 1; o < 32; o <<= 1) {
            int t = __shfl_up_sync(0xffffffffu, w, o);
            if (lane >= o) w += t;
        }
        wsum[lane] = w;
    }
    __syncthreads();
    int excl = (v - s) + (wid ? wsum[wid - 1] : 0);
    int acc = excl;
    for (int i = beg; i < end; i++) { g_rowptr[i] = acc; acc += g_deg[i]; }
    if (tid == 1023) g_rowptr[n] = acc;
}

__global__ void k_place(const int* __restrict__ ei, int e) {
    int i = blockIdx.x * blockDim.x + threadIdx.x;
    if (i >= e) return;
    int s = ei[i];
    int d = ei[e + i];
    int p = g_rowptr[d] + atomicAdd(&g_cursor[d], 1);
    g_csrc[p] = s;
    g_ccoef[p] = g_dinv[s] * g_dinv[d];
}

// ---------------------------------------------------------------------------
// Gather (warp per node)
// ---------------------------------------------------------------------------
__global__ __launch_bounds__(256)
void k_gather(const float* __restrict__ h, const float* __restrict__ bias, int n) {
    int w = (blockIdx.x * blockDim.x + threadIdx.x) >> 5;
    int lane = threadIdx.x & 31;
    if (w >= n) return;
    int beg = g_rowptr[w], end = g_rowptr[w + 1];
    float di = g_dinv[w];
    float4 hv = *(const float4*)(h + (size_t)w * CCH + lane * 4);
    float sl = di * di;
    float ax = sl * hv.x, ay = sl * hv.y, az = sl * hv.z, aw = sl * hv.w;

    int j = beg;
    for (; j + 1 < end; j += 2) {
        int s0 = g_csrc[j], s1 = g_csrc[j + 1];
        float c0 = g_ccoef[j], c1 = g_ccoef[j + 1];
        float4 v0 = *(const float4*)(h + (size_t)s0 * CCH + lane * 4);
        float4 v1 = *(const float4*)(h + (size_t)s1 * CCH + lane * 4);
        ax = fmaf(c0, v0.x, ax); ay = fmaf(c0, v0.y, ay);
        az = fmaf(c0, v0.z, az); aw = fmaf(c0, v0.w, aw);
        ax = fmaf(c1, v1.x, ax); ay = fmaf(c1, v1.y, ay);
        az = fmaf(c1, v1.z, az); aw = fmaf(c1, v1.w, aw);
    }
    if (j < end) {
        int s0 = g_csrc[j];
        float c0 = g_ccoef[j];
        float4 v0 = *(const float4*)(h + (size_t)s0 * CCH + lane * 4);
        ax = fmaf(c0, v0.x, ax); ay = fmaf(c0, v0.y, ay);
        az = fmaf(c0, v0.z, az); aw = fmaf(c0, v0.w, aw);
    }
    float b0 = bias[lane * 4 + 0], b1 = bias[lane * 4 + 1];
    float b2 = bias[lane * 4 + 2], b3 = bias[lane * 4 + 3];
    float4 o; o.x = ax + b0; o.y = ay + b1; o.z = az + b2; o.w = aw + b3;
    *(float4*)(g_pool + OFF_HC + (size_t)w * CCH + lane * 4) = o;
}

// ---------------------------------------------------------------------------
// Elementwise / BN
// ---------------------------------------------------------------------------
__global__ void k_xin(const float* __restrict__ nf, const float* __restrict__ ts,
                      const float* __restrict__ freq, const float* __restrict__ phase,
                      int n) {
    int idx = blockIdx.x * blockDim.x + threadIdx.x;
    if (idx >= n * CCH) return;
    int nn = idx >> 7, c = idx & 127;
    g_pool[OFF_XIN + (size_t)nn * 256 + c] = nf[idx];
    g_pool[OFF_XIN + (size_t)nn * 256 + 128 + c] = cosf(ts[nn] * freq[c] + phase[c]);
}

__global__ void k_bnstats(int nblocks, int n) {
    int c = threadIdx.x;
    float s = 0.f, comp = 0.f, s2 = 0.f, comp2 = 0.f;
    for (int b = 0; b < nblocks; b++) {
        float y = g_ps1[(size_t)b * CCH + c] - comp;
        float t = s + y; comp = (t - s) - y; s = t;
        float y2 = g_ps2[(size_t)b * CCH + c] - comp2;
        float t2 = s2 + y2; comp2 = (t2 - s2) - y2; s2 = t2;
    }
    float invn = 1.f / (float)n;
    float mean = s * invn;
    float var = s2 * invn - mean * mean;
    g_mean[c] = mean;
    g_scale[c] = rsqrtf(var + EPS_BN);
}

__global__ void k_bnapply(float* __restrict__ out2, int n) {
    int idx = blockIdx.x * blockDim.x + threadIdx.x;
    if (idx >= n * CCH) return;
    int c = idx & 127;
    out2[idx] = (out2[idx] - g_mean[c]) * g_scale[c];
}

// ---------------------------------------------------------------------------
// Launch
// ---------------------------------------------------------------------------
extern "C" void kernel_launch(void* const* d_in, const int* in_sizes, int n_in,
                              void* d_out, int out_size) {
    const float* nf    = (const float*)d_in[0];
    const int*   ei    = (const int*)d_in[1];        // int32 (JAX x64 off)
    const float* xp1   = (const float*)d_in[2];
    const float* xp2   = (const float*)d_in[3];
    const float* ts    = (const float*)d_in[4];
    const float* freq  = (const float*)d_in[5];
    const float* phase = (const float*)d_in[6];
    const float* mW    = (const float*)d_in[7];
    const float* mb    = (const float*)d_in[8];
    const float* W1    = (const float*)d_in[9];
    const float* b1    = (const float*)d_in[10];
    const float* g1Wih = (const float*)d_in[11];
    const float* g1Whh = (const float*)d_in[12];
    const float* g1bih = (const float*)d_in[13];
    const float* g1bhh = (const float*)d_in[14];
    const float* W2    = (const float*)d_in[15];
    const float* b2    = (const float*)d_in[16];
    const float* g2Wih = (const float*)d_in[17];
    const float* g2Whh = (const float*)d_in[18];
    const float* g2bih = (const float*)d_in[19];
    const float* g2bhh = (const float*)d_in[20];
    const float* skW   = (const float*)d_in[21];
    const float* skb   = (const float*)d_in[22];

    float* out = (float*)d_out;

    const int n = in_sizes[0] / CCH;
    const int e = in_sizes[1] / 2;
    const int nc = n * CCH;

    float* H1 = out;
    float* H2 = out + nc;

    const int T = 256;
    dim3 gN(ceildiv(n, T));
    dim3 gE(ceildiv(e, T));
    dim3 gNC(ceildiv(nc, T));
    dim3 gGat(ceildiv(n * 32, T));
    dim3 gM(ceildiv(n, BM));
    int nbg = ceildiv(n, 32);

    // CSR build
    k_zero <<<gN, T>>>(n);
    k_count<<<gE, T>>>(ei, e);
    k_dinv <<<gN, T>>>(n);
    k_scan <<<1, 1024>>>(n);
    k_place<<<gE, T>>>(ei, e);

    // time encode + merge + skip
    k_xin<<<gNC, T>>>(nf, ts, freq, phase, n);
    gemm_merge<<<gM, 256>>>(mW, mb, n);
    gemm_skip <<<gM, 256>>>(skW, skb, n);

    // ---- layer 1 ----
    gemm_w1<<<gM, 256>>>(W1, H2, n);
    k_gather<<<gGat, T>>>(H2, b1, n);
    gru_fused<1><<<nbg, 512>>>(g1Wih, g1Whh, g1bih, g1bhh, xp1, H1, n);

    // ---- layer 2 ----
    gemm_w2<<<gM, 256>>>(H1, W2, H2, n);
    k_gather<<<gGat, T>>>(H2, b2, n);
    gru_fused<2><<<nbg, 512>>>(g2Wih, g2Whh, g2bih, g2bhh, xp2, H2, n);

    // batchnorm
    k_bnstats<<<1, 128>>>(nbg, n);
    k_bnapply<<<gNC, T>>>(H2, n);
}

// round 8
// speedup vs baseline: 1.2125x; 1.0250x over previous
#include <cuda_runtime.h>
#include <math.h>

#define NMAX   50000
#define EMAX   1600000
#define CCH    128
#define EPS_BN 1e-5f
#define NBG    ((NMAX + 31) / 32)

static inline int ceildiv(int a, int b) { return (a + b - 1) / b; }

// ---------------------------------------------------------------------------
// Packed f32x2 helpers
// ---------------------------------------------------------------------------
__device__ __forceinline__ unsigned long long dup2(float x) {
    unsigned long long r;
    asm("mov.b64 %0, {%1,%1};" : "=l"(r) : "f"(x));
    return r;
}
__device__ __forceinline__ void fma2(unsigned long long& d,
                                     unsigned long long a, unsigned long long b) {
    asm("fma.rn.f32x2 %0, %1, %2, %0;" : "+l"(d) : "l"(a), "l"(b));
}
__device__ __forceinline__ float2 unpk2(unsigned long long v) {
    float2 f;
    asm("mov.b64 {%0,%1}, %2;" : "=f"(f.x), "=f"(f.y) : "l"(v));
    return f;
}

// ---------------------------------------------------------------------------
// Device scratch
// ---------------------------------------------------------------------------
#define OFF_HC  0
#define OFF_X   ((size_t)NMAX * 256)
#define OFF_SK  ((size_t)NMAX * 384)

__device__ __align__(16) float g_pool[(size_t)NMAX * 512];
__device__ float g_dinv[NMAX];
__device__ int   g_deg[NMAX];
__device__ int   g_cursor[NMAX];
__device__ int   g_rowptr[NMAX + 1];
__device__ __align__(8) int2 g_edge[EMAX];     // (src, coef as bits)
__device__ float g_ps1[(size_t)NBG * CCH];
__device__ float g_ps2[(size_t)NBG * CCH];
__device__ float g_mean[CCH];
__device__ float g_scale[CCH];

// ---------------------------------------------------------------------------
// SGEMM core pieces (BM=128, BK=16, 256 threads, f32x2 inner loop)
// ---------------------------------------------------------------------------
#define BM 128
#define BK 16
#define SP 132

__device__ __forceinline__
void sgemm_tail(const float* __restrict__ bias, float* __restrict__ C,
                unsigned long long (&acc2)[8][4], int M) {
    const int tid = threadIdx.x;
    const int tx = tid & 15;
    const int ty = tid >> 4;
    const int bm = blockIdx.x * BM;
    #pragma unroll
    for (int i = 0; i < 8; i++) {
        int grow = bm + ty * 8 + i;
        if (grow >= M) break;
        #pragma unroll
        for (int j = 0; j < 4; j++) {
            int gcol = tx * 8 + j * 2;
            float2 v = unpk2(acc2[i][j]);
            if (bias) { v.x += bias[gcol]; v.y += bias[gcol + 1]; }
            *(float2*)(C + (size_t)grow * CCH + gcol) = v;
        }
    }
}

__device__ __forceinline__
void sgemm_mainloop(float* As, float* Bs, unsigned long long (&acc2)[8][4]) {
    const int tid = threadIdx.x;
    const int tx = tid & 15;
    const int ty = tid >> 4;
    #pragma unroll
    for (int k = 0; k < BK; k++) {
        unsigned long long ra2[8], rb2[4];
        #pragma unroll
        for (int i = 0; i < 8; i++) ra2[i] = dup2(As[k * SP + ty * 8 + i]);
        #pragma unroll
        for (int j = 0; j < 4; j++)
            rb2[j] = *(const unsigned long long*)(Bs + k * SP + tx * 8 + j * 2);
        #pragma unroll
        for (int i = 0; i < 8; i++)
            #pragma unroll
            for (int j = 0; j < 4; j++)
                fma2(acc2[i][j], ra2[i], rb2[j]);
    }
}

// Plain GEMM: C[Mx128] = A[MxK] @ B[128xK]^T (+bias)
__device__ __forceinline__
void sgemm_body(const float* __restrict__ A, const float* __restrict__ B,
                const float* __restrict__ bias, float* __restrict__ C,
                int M, int K) {
    __shared__ __align__(16) float As[BK * SP];
    __shared__ __align__(16) float Bs[BK * SP];
    const int bm = blockIdx.x * BM;
    const int tid = threadIdx.x;

    unsigned long long acc2[8][4];
    #pragma unroll
    for (int i = 0; i < 8; i++)
        #pragma unroll
        for (int j = 0; j < 4; j++) acc2[i][j] = 0ull;

    for (int k0 = 0; k0 < K; k0 += BK) {
        #pragma unroll
        for (int i = 0; i < 8; i++) {
            int idx = tid + i * 256;
            int k = idx & 15, r = idx >> 4;
            int grow = bm + r;
            As[k * SP + r] = (grow < M) ? A[(size_t)grow * K + k0 + k] : 0.f;
        }
        #pragma unroll
        for (int i = 0; i < 8; i++) {
            int idx = tid + i * 256;
            int k = idx & 15, c = idx >> 4;
            Bs[k * SP + c] = B[(size_t)c * K + k0 + k];
        }
        __syncthreads();
        sgemm_mainloop(As, Bs, acc2);
        __syncthreads();
    }
    sgemm_tail(bias, C, acc2, M);
}

// Merge GEMM with fused time-encode: A = [nf | cos(ts*freq+phase)], K=256
__global__ __launch_bounds__(256, 2)
void gemm_merge(const float* __restrict__ nf, const float* __restrict__ ts,
                const float* __restrict__ freq, const float* __restrict__ phase,
                const float* __restrict__ W, const float* __restrict__ b, int M) {
    __shared__ __align__(16) float As[BK * SP];
    __shared__ __align__(16) float Bs[BK * SP];
    const int bm = blockIdx.x * BM;
    const int tid = threadIdx.x;

    unsigned long long acc2[8][4];
    #pragma unroll
    for (int i = 0; i < 8; i++)
        #pragma unroll
        for (int j = 0; j < 4; j++) acc2[i][j] = 0ull;

    for (int k0 = 0; k0 < 256; k0 += BK) {
        #pragma unroll
        for (int i = 0; i < 8; i++) {
            int idx = tid + i * 256;
            int k = idx & 15, r = idx >> 4;
            int grow = bm + r;
            int kk = k0 + k;
            float v = 0.f;
            if (grow < M) {
                if (kk < 128) v = nf[(size_t)grow * 128 + kk];
                else          v = cosf(ts[grow] * freq[kk - 128] + phase[kk - 128]);
            }
            As[k * SP + r] = v;
        }
        #pragma unroll
        for (int i = 0; i < 8; i++) {
            int idx = tid + i * 256;
            int k = idx & 15, c = idx >> 4;
            Bs[k * SP + c] = W[(size_t)c * 256 + k0 + k];
        }
        __syncthreads();
        sgemm_mainloop(As, Bs, acc2);
        __syncthreads();
    }
    sgemm_tail(b, g_pool + OFF_X, acc2, M);
}

__global__ __launch_bounds__(256, 2)
void gemm_skip(const float* __restrict__ W, const float* __restrict__ b, int M) {
    sgemm_body(g_pool + OFF_X, W, b, g_pool + OFF_SK, M, 128);
}
__global__ __launch_bounds__(256, 2)
void gemm_w1(const float* __restrict__ W, float* __restrict__ h, int M) {
    sgemm_body(g_pool + OFF_X, W, nullptr, h, M, 128);
}
__global__ __launch_bounds__(256, 2)
void gemm_w2(const float* __restrict__ H1, const float* __restrict__ W,
             float* __restrict__ h, int M) {
    sgemm_body(H1, W, nullptr, h, M, 128);
}

// ---------------------------------------------------------------------------
// Fused GRU GEMM+gate (unchanged from R7)
// ---------------------------------------------------------------------------
#define GBK 8
#define BPad 386
#define APad 33

template<int LAYER>
__global__ __launch_bounds__(512, 1)
void gru_fused(const float* __restrict__ Wih, const float* __restrict__ Whh,
               const float* __restrict__ bih, const float* __restrict__ bhh,
               const float* __restrict__ xprev, float* __restrict__ outH, int n) {
    __shared__ __align__(16) float Bi[GBK * BPad];
    __shared__ __align__(16) float Bh[GBK * BPad];
    __shared__ __align__(16) float Ahc[GBK * APad];
    __shared__ __align__(16) float Axp[GBK * APad];

    const int tid = threadIdx.x;
    const int tx = tid & 63;
    const int ty = tid >> 6;
    const int bm = blockIdx.x * 32;
    const float* hc = g_pool + OFF_HC;

    unsigned long long ai2[4][3], ah2[4][3];
    #pragma unroll
    for (int i = 0; i < 4; i++)
        #pragma unroll
        for (int g = 0; g < 3; g++) { ai2[i][g] = 0ull; ah2[i][g] = 0ull; }

    for (int k0 = 0; k0 < 128; k0 += GBK) {
        #pragma unroll
        for (int i = 0; i < 6; i++) {
            int idx = tid + i * 512;
            int c = idx >> 3, k = idx & 7;
            Bi[k * BPad + c] = Wih[(size_t)c * 128 + k0 + k];
            Bh[k * BPad + c] = Whh[(size_t)c * 128 + k0 + k];
        }
        {
            int matsel = tid >> 8;
            int rem = tid & 255;
            int r = rem >> 3, k = rem & 7;
            int grow = bm + r;
            const float* src = matsel ? xprev : hc;
            float v = (grow < n) ? src[(size_t)grow * 128 + k0 + k] : 0.f;
            if (matsel) Axp[k * APad + r] = v;
            else        Ahc[k * APad + r] = v;
        }
        __syncthreads();

        #pragma unroll
        for (int k = 0; k < GBK; k++) {
            unsigned long long rhc2[4], rxp2[4], wi2[3], wh2[3];
            #pragma unroll
            for (int i = 0; i < 4; i++) {
                rhc2[i] = dup2(Ahc[k * APad + ty * 4 + i]);
                rxp2[i] = dup2(Axp[k * APad + ty * 4 + i]);
            }
            #pragma unroll
            for (int g = 0; g < 3; g++) {
                int cb = g * 128 + tx * 2;
                wi2[g] = *(const unsigned long long*)(Bi + k * BPad + cb);
                wh2[g] = *(const unsigned long long*)(Bh + k * BPad + cb);
            }
            #pragma unroll
            for (int i = 0; i < 4; i++)
                #pragma unroll
                for (int g = 0; g < 3; g++) {
                    fma2(ai2[i][g], rhc2[i], wi2[g]);
                    fma2(ah2[i][g], rxp2[i], wh2[g]);
                }
        }
        __syncthreads();
    }

    float bi_[3][2], bh_[3][2];
    #pragma unroll
    for (int g = 0; g < 3; g++)
        #pragma unroll
        for (int q = 0; q < 2; q++) {
            bi_[g][q] = bih[g * 128 + tx * 2 + q];
            bh_[g][q] = bhh[g * 128 + tx * 2 + q];
        }

    float ls[2], ls2[2];
    ls[0] = ls[1] = ls2[0] = ls2[1] = 0.f;

    #pragma unroll
    for (int i = 0; i < 4; i++) {
        int row = bm + ty * 4 + i;
        if (row >= n) break;
        float2 aiv[3], ahv[3];
        #pragma unroll
        for (int g = 0; g < 3; g++) { aiv[g] = unpk2(ai2[i][g]); ahv[g] = unpk2(ah2[i][g]); }
        #pragma unroll
        for (int q = 0; q < 2; q++) {
            int c = tx * 2 + q;
            float a0 = q ? aiv[0].y : aiv[0].x, h0 = q ? ahv[0].y : ahv[0].x;
            float a1 = q ? aiv[1].y : aiv[1].x, h1 = q ? ahv[1].y : ahv[1].x;
            float a2 = q ? aiv[2].y : aiv[2].x, h2 = q ? ahv[2].y : ahv[2].x;
            float gr = (a0 + bi_[0][q]) + (h0 + bh_[0][q]);
            float gz = (a1 + bi_[1][q]) + (h1 + bh_[1][q]);
            float r = 1.f / (1.f + expf(-gr));
            float z = 1.f / (1.f + expf(-gz));
            float nn = tanhf((a2 + bi_[2][q]) + r * (h2 + bh_[2][q]));
            float hprev = xprev[(size_t)row * 128 + c];
            float val = (1.f - z) * nn + z * hprev;
            if (LAYER == 1) {
                outH[(size_t)row * 128 + c] = fmaxf(val, 0.f);
            } else {
                val += g_pool[OFF_SK + (size_t)row * 128 + c];
                outH[(size_t)row * 128 + c] = val;
                ls[q] += val;
                ls2[q] += val * val;
            }
        }
    }

    if (LAYER == 2) {
        __syncthreads();
        float* red = Bi;
        red[(tx * 2 + 0) * 8 + ty] = ls[0];
        red[(tx * 2 + 1) * 8 + ty] = ls[1];
        float* red2 = Bh;
        red2[(tx * 2 + 0) * 8 + ty] = ls2[0];
        red2[(tx * 2 + 1) * 8 + ty] = ls2[1];
        __syncthreads();
        if (tid < 128) {
            float s = 0.f, s2 = 0.f;
            #pragma unroll
            for (int t = 0; t < 8; t++) { s += red[tid * 8 + t]; s2 += red2[tid * 8 + t]; }
            g_ps1[(size_t)blockIdx.x * CCH + tid] = s;
            g_ps2[(size_t)blockIdx.x * CCH + tid] = s2;
        }
    }
}

// ---------------------------------------------------------------------------
// CSR build
// ---------------------------------------------------------------------------
__global__ void k_prep(int n) {
    int i = blockIdx.x * blockDim.x + threadIdx.x;
    if (i < n) { g_deg[i] = 0; g_cursor[i] = 0; }
}
__global__ void k_count(const int* __restrict__ ei, int e) {
    int i = blockIdx.x * blockDim.x + threadIdx.x;
    if (i < e) atomicAdd(&g_deg[ei[e + i]], 1);
}

// coalesced tiled scan + dinv (1 block, 1024 threads)
__global__ void k_scan_dinv(int n) {
    __shared__ int wsum[32];
    const int tid = threadIdx.x;
    const int lane = tid & 31, wid = tid >> 5;
    int base = 0;
    for (int t0 = 0; t0 < n; t0 += 1024) {
        int i = t0 + tid;
        int d = (i < n) ? g_deg[i] : 0;
        int v = d;
        #pragma unroll
        for (int o = 1; o < 32; o <<= 1) {
            int t = __shfl_up_sync(0xffffffffu, v, o);
            if (lane >= o) v += t;
        }
        if (lane == 31) wsum[wid] = v;
        __syncthreads();
        if (wid == 0) {
            int w = wsum[lane];
            #pragma unroll
            for (int o = 1; o < 32; o <<= 1) {
                int t = __shfl_up_sync(0xffffffffu, w, o);
                if (lane >= o) w += t;
            }
            wsum[lane] = w;
        }
        __syncthreads();
        int excl = (v - d) + (wid ? wsum[wid - 1] : 0);
        if (i < n) {
            g_rowptr[i] = base + excl;
            g_dinv[i] = rsqrtf((float)(d + 1));
        }
        base += wsum[31];
        __syncthreads();
    }
    if (tid == 0) g_rowptr[n] = base;
}

__global__ void k_place(const int* __restrict__ ei, int e) {
    int i = blockIdx.x * blockDim.x + threadIdx.x;
    if (i >= e) return;
    int s = ei[i];
    int d = ei[e + i];
    int p = g_rowptr[d] + atomicAdd(&g_cursor[d], 1);
    g_edge[p] = make_int2(s, __float_as_int(g_dinv[s] * g_dinv[d]));
}

// ---------------------------------------------------------------------------
// Gather (warp per node), int2 edges, unroll 4
// ---------------------------------------------------------------------------
__global__ __launch_bounds__(256)
void k_gather(const float* __restrict__ h, const float* __restrict__ bias, int n) {
    int w = (blockIdx.x * blockDim.x + threadIdx.x) >> 5;
    int lane = threadIdx.x & 31;
    if (w >= n) return;
    int beg = g_rowptr[w], end = g_rowptr[w + 1];
    float di = g_dinv[w];
    float4 hv = *(const float4*)(h + (size_t)w * CCH + lane * 4);
    float sl = di * di;
    float ax = sl * hv.x, ay = sl * hv.y, az = sl * hv.z, aw = sl * hv.w;

    int j = beg;
    for (; j + 3 < end; j += 4) {
        int2 e0 = g_edge[j],     e1 = g_edge[j + 1];
        int2 e2 = g_edge[j + 2], e3 = g_edge[j + 3];
        float4 v0 = *(const float4*)(h + (size_t)e0.x * CCH + lane * 4);
        float4 v1 = *(const float4*)(h + (size_t)e1.x * CCH + lane * 4);
        float4 v2 = *(const float4*)(h + (size_t)e2.x * CCH + lane * 4);
        float4 v3 = *(const float4*)(h + (size_t)e3.x * CCH + lane * 4);
        float c0 = __int_as_float(e0.y), c1 = __int_as_float(e1.y);
        float c2 = __int_as_float(e2.y), c3 = __int_as_float(e3.y);
        ax = fmaf(c0, v0.x, ax); ay = fmaf(c0, v0.y, ay);
        az = fmaf(c0, v0.z, az); aw = fmaf(c0, v0.w, aw);
        ax = fmaf(c1, v1.x, ax); ay = fmaf(c1, v1.y, ay);
        az = fmaf(c1, v1.z, az); aw = fmaf(c1, v1.w, aw);
        ax = fmaf(c2, v2.x, ax); ay = fmaf(c2, v2.y, ay);
        az = fmaf(c2, v2.z, az); aw = fmaf(c2, v2.w, aw);
        ax = fmaf(c3, v3.x, ax); ay = fmaf(c3, v3.y, ay);
        az = fmaf(c3, v3.z, az); aw = fmaf(c3, v3.w, aw);
    }
    for (; j < end; j++) {
        int2 e0 = g_edge[j];
        float c0 = __int_as_float(e0.y);
        float4 v0 = *(const float4*)(h + (size_t)e0.x * CCH + lane * 4);
        ax = fmaf(c0, v0.x, ax); ay = fmaf(c0, v0.y, ay);
        az = fmaf(c0, v0.z, az); aw = fmaf(c0, v0.w, aw);
    }
    float b0 = bias[lane * 4 + 0], b1 = bias[lane * 4 + 1];
    float b2 = bias[lane * 4 + 2], b3 = bias[lane * 4 + 3];
    float4 o; o.x = ax + b0; o.y = ay + b1; o.z = az + b2; o.w = aw + b3;
    *(float4*)(g_pool + OFF_HC + (size_t)w * CCH + lane * 4) = o;
}

// ---------------------------------------------------------------------------
// BN
// ---------------------------------------------------------------------------
__global__ void k_bnstats(int nblocks, int n) {
    int c = threadIdx.x;
    float s = 0.f, comp = 0.f, s2 = 0.f, comp2 = 0.f;
    for (int b = 0; b < nblocks; b++) {
        float y = g_ps1[(size_t)b * CCH + c] - comp;
        float t = s + y; comp = (t - s) - y; s = t;
        float y2 = g_ps2[(size_t)b * CCH + c] - comp2;
        float t2 = s2 + y2; comp2 = (t2 - s2) - y2; s2 = t2;
    }
    float invn = 1.f / (float)n;
    float mean = s * invn;
    float var = s2 * invn - mean * mean;
    g_mean[c] = mean;
    g_scale[c] = rsqrtf(var + EPS_BN);
}

__global__ void k_bnapply(float* __restrict__ out2, int n) {
    int idx = blockIdx.x * blockDim.x + threadIdx.x;
    if (idx >= n * CCH) return;
    int c = idx & 127;
    out2[idx] = (out2[idx] - g_mean[c]) * g_scale[c];
}

// ---------------------------------------------------------------------------
// Launch — CSR chain forked onto a second stream, joined before gather1.
// ---------------------------------------------------------------------------
extern "C" void kernel_launch(void* const* d_in, const int* in_sizes, int n_in,
                              void* d_out, int out_size) {
    const float* nf    = (const float*)d_in[0];
    const int*   ei    = (const int*)d_in[1];
    const float* xp1   = (const float*)d_in[2];
    const float* xp2   = (const float*)d_in[3];
    const float* ts    = (const float*)d_in[4];
    const float* freq  = (const float*)d_in[5];
    const float* phase = (const float*)d_in[6];
    const float* mW    = (const float*)d_in[7];
    const float* mb    = (const float*)d_in[8];
    const float* W1    = (const float*)d_in[9];
    const float* b1    = (const float*)d_in[10];
    const float* g1Wih = (const float*)d_in[11];
    const float* g1Whh = (const float*)d_in[12];
    const float* g1bih = (const float*)d_in[13];
    const float* g1bhh = (const float*)d_in[14];
    const float* W2    = (const float*)d_in[15];
    const float* b2    = (const float*)d_in[16];
    const float* g2Wih = (const float*)d_in[17];
    const float* g2Whh = (const float*)d_in[18];
    const float* g2bih = (const float*)d_in[19];
    const float* g2bhh = (const float*)d_in[20];
    const float* skW   = (const float*)d_in[21];
    const float* skb   = (const float*)d_in[22];

    float* out = (float*)d_out;

    const int n = in_sizes[0] / CCH;
    const int e = in_sizes[1] / 2;
    const int nc = n * CCH;

    float* H1 = out;
    float* H2 = out + nc;

    const int T = 256;
    dim3 gN(ceildiv(n, T));
    dim3 gE(ceildiv(e, T));
    dim3 gNC(ceildiv(nc, T));
    dim3 gGat(ceildiv(n * 32, T));
    dim3 gM(ceildiv(n, BM));
    int nbg = ceildiv(n, 32);

    // one-time side-stream + events (created outside capture on first call;
    // per-call work is identical every time)
    static cudaStream_t s2 = nullptr;
    static cudaEvent_t evFork = nullptr, evJoin = nullptr;
    if (!s2) {
        cudaStreamCreateWithFlags(&s2, cudaStreamNonBlocking);
        cudaEventCreateWithFlags(&evFork, cudaEventDisableTiming);
        cudaEventCreateWithFlags(&evJoin, cudaEventDisableTiming);
    }

    // fork: CSR chain on s2
    cudaEventRecord(evFork, 0);
    cudaStreamWaitEvent(s2, evFork, 0);
    k_prep     <<<gN, T, 0, s2>>>(n);
    k_count    <<<gE, T, 0, s2>>>(ei, e);
    k_scan_dinv<<<1, 1024, 0, s2>>>(n);
    k_place    <<<gE, T, 0, s2>>>(ei, e);
    cudaEventRecord(evJoin, s2);

    // main: GEMM chain (merge has fused time-encode)
    gemm_merge<<<gM, 256>>>(nf, ts, freq, phase, mW, mb, n);
    gemm_skip <<<gM, 256>>>(skW, skb, n);
    gemm_w1   <<<gM, 256>>>(W1, H2, n);

    // join: gather needs CSR
    cudaStreamWaitEvent(0, evJoin, 0);

    // ---- layer 1 ----
    k_gather<<<gGat, T>>>(H2, b1, n);
    gru_fused<1><<<nbg, 512>>>(g1Wih, g1Whh, g1bih, g1bhh, xp1, H1, n);

    // ---- layer 2 ----
    gemm_w2<<<gM, 256>>>(H1, W2, H2, n);
    k_gather<<<gGat, T>>>(H2, b2, n);
    gru_fused<2><<<nbg, 512>>>(g2Wih, g2Whh, g2bih, g2bhh, xp2, H2, n);

    // batchnorm
    k_bnstats<<<1, 128>>>(nbg, n);
    k_bnapply<<<gNC, T>>>(H2, n);
}

// round 9
// speedup vs baseline: 1.3272x; 1.0945x over previous
#include <cuda_runtime.h>
#include <math.h>

#define NMAX   50000
#define EMAX   1600000
#define CCH    128
#define EPS_BN 1e-5f
#define NBG    ((NMAX + 31) / 32)

static inline int ceildiv(int a, int b) { return (a + b - 1) / b; }

// ---------------------------------------------------------------------------
// Packed f32x2 helpers
// ---------------------------------------------------------------------------
__device__ __forceinline__ unsigned long long dup2(float x) {
    unsigned long long r;
    asm("mov.b64 %0, {%1,%1};" : "=l"(r) : "f"(x));
    return r;
}
__device__ __forceinline__ void fma2(unsigned long long& d,
                                     unsigned long long a, unsigned long long b) {
    asm("fma.rn.f32x2 %0, %1, %2, %0;" : "+l"(d) : "l"(a), "l"(b));
}
__device__ __forceinline__ float2 unpk2(unsigned long long v) {
    float2 f;
    asm("mov.b64 {%0,%1}, %2;" : "=f"(f.x), "=f"(f.y) : "l"(v));
    return f;
}

// ---------------------------------------------------------------------------
// Device scratch
// ---------------------------------------------------------------------------
#define OFF_HC  0
#define OFF_X   ((size_t)NMAX * 256)
#define OFF_SK  ((size_t)NMAX * 384)

__device__ __align__(16) float g_pool[(size_t)NMAX * 512];
__device__ float g_dinv[NMAX];
__device__ int   g_deg[NMAX];
__device__ int   g_cursor[NMAX];
__device__ int   g_rowptr[NMAX + 1];
__device__ __align__(8) int2 g_edge[EMAX];
__device__ float g_ps1[(size_t)NBG * CCH];
__device__ float g_ps2[(size_t)NBG * CCH];
__device__ float g_mean[CCH];
__device__ float g_scale[CCH];

// ---------------------------------------------------------------------------
// SGEMM (double-buffered): C[Mx128] = A[MxK] @ B[128xK]^T (+bias)
// BM=128, BK=16, 256 threads
// ---------------------------------------------------------------------------
#define BM 128
#define BK 16
#define SP 132

__device__ __forceinline__
void sgemm_mainloop(const float* __restrict__ As, const float* __restrict__ Bs,
                    unsigned long long (&acc2)[8][4]) {
    const int tid = threadIdx.x;
    const int tx = tid & 15;
    const int ty = tid >> 4;
    #pragma unroll
    for (int k = 0; k < BK; k++) {
        unsigned long long ra2[8], rb2[4];
        #pragma unroll
        for (int i = 0; i < 8; i++) ra2[i] = dup2(As[k * SP + ty * 8 + i]);
        #pragma unroll
        for (int j = 0; j < 4; j++)
            rb2[j] = *(const unsigned long long*)(Bs + k * SP + tx * 8 + j * 2);
        #pragma unroll
        for (int i = 0; i < 8; i++)
            #pragma unroll
            for (int j = 0; j < 4; j++)
                fma2(acc2[i][j], ra2[i], rb2[j]);
    }
}

__device__ __forceinline__
void sgemm_tail(const float* __restrict__ bias, float* __restrict__ C,
                unsigned long long (&acc2)[8][4], int M) {
    const int tid = threadIdx.x;
    const int tx = tid & 15;
    const int ty = tid >> 4;
    const int bm = blockIdx.x * BM;
    #pragma unroll
    for (int i = 0; i < 8; i++) {
        int grow = bm + ty * 8 + i;
        if (grow >= M) break;
        #pragma unroll
        for (int j = 0; j < 4; j++) {
            int gcol = tx * 8 + j * 2;
            float2 v = unpk2(acc2[i][j]);
            if (bias) { v.x += bias[gcol]; v.y += bias[gcol + 1]; }
            *(float2*)(C + (size_t)grow * CCH + gcol) = v;
        }
    }
}

// AF(i, k, r) must yield A[grow][k0+k]; generic via lambda-like functor macro.
// Plain double-buffered GEMM.
__device__ __forceinline__
void sgemm_db(const float* __restrict__ A, const float* __restrict__ B,
              const float* __restrict__ bias, float* __restrict__ C,
              int M, int K) {
    __shared__ __align__(16) float As[2][BK * SP];
    __shared__ __align__(16) float Bs[2][BK * SP];
    const int bm = blockIdx.x * BM;
    const int tid = threadIdx.x;
    const int lk = tid & 15;        // loader k
    const int lr = tid >> 4;        // loader row/col base (0..15), +i*16

    float pa[8], pb[8];
    // tile 0 prefetch
    #pragma unroll
    for (int i = 0; i < 8; i++) {
        int r = lr + i * 16;
        int grow = bm + r;
        pa[i] = (grow < M) ? A[(size_t)grow * K + lk] : 0.f;
        pb[i] = B[(size_t)r * K + lk];   // r is col index for B (0..127)
    }
    #pragma unroll
    for (int i = 0; i < 8; i++) {
        int r = lr + i * 16;
        As[0][lk * SP + r] = pa[i];
        Bs[0][lk * SP + r] = pb[i];
    }
    __syncthreads();

    unsigned long long acc2[8][4];
    #pragma unroll
    for (int i = 0; i < 8; i++)
        #pragma unroll
        for (int j = 0; j < 4; j++) acc2[i][j] = 0ull;

    const int nT = K / BK;
    for (int t = 0; t < nT; t++) {
        if (t + 1 < nT) {
            int k0n = (t + 1) * BK;
            #pragma unroll
            for (int i = 0; i < 8; i++) {
                int r = lr + i * 16;
                int grow = bm + r;
                pa[i] = (grow < M) ? A[(size_t)grow * K + k0n + lk] : 0.f;
                pb[i] = B[(size_t)r * K + k0n + lk];
            }
        }
        sgemm_mainloop(As[t & 1], Bs[t & 1], acc2);
        if (t + 1 < nT) {
            float* An = As[(t + 1) & 1];
            float* Bn = Bs[(t + 1) & 1];
            #pragma unroll
            for (int i = 0; i < 8; i++) {
                int r = lr + i * 16;
                An[lk * SP + r] = pa[i];
                Bn[lk * SP + r] = pb[i];
            }
            __syncthreads();
        }
    }
    sgemm_tail(bias, C, acc2, M);
}

// Merge GEMM (K=256) with fused time-encode, double-buffered.
__global__ __launch_bounds__(256, 2)
void gemm_merge(const float* __restrict__ nf, const float* __restrict__ ts,
                const float* __restrict__ freq, const float* __restrict__ phase,
                const float* __restrict__ W, const float* __restrict__ b, int M) {
    __shared__ __align__(16) float As[2][BK * SP];
    __shared__ __align__(16) float Bs[2][BK * SP];
    const int bm = blockIdx.x * BM;
    const int tid = threadIdx.x;
    const int lk = tid & 15;
    const int lr = tid >> 4;
    const int K = 256;

    float pa[8], pb[8];
    #pragma unroll
    for (int i = 0; i < 8; i++) {
        int r = lr + i * 16;
        int grow = bm + r;
        pa[i] = (grow < M) ? nf[(size_t)grow * 128 + lk] : 0.f;   // k0=0 < 128
        pb[i] = W[(size_t)r * K + lk];
    }
    #pragma unroll
    for (int i = 0; i < 8; i++) {
        int r = lr + i * 16;
        As[0][lk * SP + r] = pa[i];
        Bs[0][lk * SP + r] = pb[i];
    }
    __syncthreads();

    unsigned long long acc2[8][4];
    #pragma unroll
    for (int i = 0; i < 8; i++)
        #pragma unroll
        for (int j = 0; j < 4; j++) acc2[i][j] = 0ull;

    const int nT = K / BK;   // 16
    for (int t = 0; t < nT; t++) {
        if (t + 1 < nT) {
            int k0n = (t + 1) * BK;
            int kk = k0n + lk;
            #pragma unroll
            for (int i = 0; i < 8; i++) {
                int r = lr + i * 16;
                int grow = bm + r;
                float v = 0.f;
                if (grow < M) {
                    if (kk < 128) v = nf[(size_t)grow * 128 + kk];
                    else          v = cosf(ts[grow] * freq[kk - 128] + phase[kk - 128]);
                }
                pa[i] = v;
                pb[i] = W[(size_t)r * K + k0n + lk];
            }
        }
        sgemm_mainloop(As[t & 1], Bs[t & 1], acc2);
        if (t + 1 < nT) {
            float* An = As[(t + 1) & 1];
            float* Bn = Bs[(t + 1) & 1];
            #pragma unroll
            for (int i = 0; i < 8; i++) {
                int r = lr + i * 16;
                An[lk * SP + r] = pa[i];
                Bn[lk * SP + r] = pb[i];
            }
            __syncthreads();
        }
    }
    sgemm_tail(b, g_pool + OFF_X, acc2, M);
}

__global__ __launch_bounds__(256, 2)
void gemm_skip(const float* __restrict__ W, const float* __restrict__ b, int M) {
    sgemm_db(g_pool + OFF_X, W, b, g_pool + OFF_SK, M, 128);
}
__global__ __launch_bounds__(256, 2)
void gemm_w1(const float* __restrict__ W, float* __restrict__ h, int M) {
    sgemm_db(g_pool + OFF_X, W, nullptr, h, M, 128);
}
__global__ __launch_bounds__(256, 2)
void gemm_w2(const float* __restrict__ H1, const float* __restrict__ W,
             float* __restrict__ h, int M) {
    sgemm_db(H1, W, nullptr, h, M, 128);
}

// ---------------------------------------------------------------------------
// Fused GRU GEMM+gate, double-buffered. 32 rows x 384 cols, both matrices.
// ---------------------------------------------------------------------------
#define GBK 8
#define BPad 386
#define APad 33

template<int LAYER>
__global__ __launch_bounds__(512, 1)
void gru_fused(const float* __restrict__ Wih, const float* __restrict__ Whh,
               const float* __restrict__ bih, const float* __restrict__ bhh,
               const float* __restrict__ xprev, float* __restrict__ outH, int n) {
    __shared__ __align__(16) float Bi[2][GBK * BPad];
    __shared__ __align__(16) float Bh[2][GBK * BPad];
    __shared__ __align__(16) float Ahc[2][GBK * APad];
    __shared__ __align__(16) float Axp[2][GBK * APad];

    const int tid = threadIdx.x;
    const int tx = tid & 63;
    const int ty = tid >> 6;
    const int bm = blockIdx.x * 32;
    const float* hc = g_pool + OFF_HC;

    // loader indices
    const int bc = tid >> 3;            // weight col for i<… (c = bc + i*64? no: idx pattern)
    const int bk = tid & 7;
    const int amat = tid >> 8;          // 0: hc, 1: xprev
    const int arem = tid & 255;
    const int ar = arem >> 3;
    const int ak = arem & 7;

    float pbi[6], pbh[6], pav;
    // tile 0
    #pragma unroll
    for (int i = 0; i < 6; i++) {
        int c = bc + i * 64;
        pbi[i] = Wih[(size_t)c * 128 + bk];
        pbh[i] = Whh[(size_t)c * 128 + bk];
    }
    {
        int grow = bm + ar;
        const float* src = amat ? xprev : hc;
        pav = (grow < n) ? src[(size_t)grow * 128 + ak] : 0.f;
    }
    #pragma unroll
    for (int i = 0; i < 6; i++) {
        int c = bc + i * 64;
        Bi[0][bk * BPad + c] = pbi[i];
        Bh[0][bk * BPad + c] = pbh[i];
    }
    if (amat) Axp[0][ak * APad + ar] = pav;
    else      Ahc[0][ak * APad + ar] = pav;
    __syncthreads();

    unsigned long long ai2[4][3], ah2[4][3];
    #pragma unroll
    for (int i = 0; i < 4; i++)
        #pragma unroll
        for (int g = 0; g < 3; g++) { ai2[i][g] = 0ull; ah2[i][g] = 0ull; }

    const int nT = 128 / GBK;   // 16
    for (int t = 0; t < nT; t++) {
        if (t + 1 < nT) {
            int k0n = (t + 1) * GBK;
            #pragma unroll
            for (int i = 0; i < 6; i++) {
                int c = bc + i * 64;
                pbi[i] = Wih[(size_t)c * 128 + k0n + bk];
                pbh[i] = Whh[(size_t)c * 128 + k0n + bk];
            }
            int grow = bm + ar;
            const float* src = amat ? xprev : hc;
            pav = (grow < n) ? src[(size_t)grow * 128 + k0n + ak] : 0.f;
        }

        const float* cBi = Bi[t & 1];
        const float* cBh = Bh[t & 1];
        const float* cAh = Ahc[t & 1];
        const float* cAx = Axp[t & 1];
        #pragma unroll
        for (int k = 0; k < GBK; k++) {
            unsigned long long rhc2[4], rxp2[4], wi2[3], wh2[3];
            #pragma unroll
            for (int i = 0; i < 4; i++) {
                rhc2[i] = dup2(cAh[k * APad + ty * 4 + i]);
                rxp2[i] = dup2(cAx[k * APad + ty * 4 + i]);
            }
            #pragma unroll
            for (int g = 0; g < 3; g++) {
                int cb = g * 128 + tx * 2;
                wi2[g] = *(const unsigned long long*)(cBi + k * BPad + cb);
                wh2[g] = *(const unsigned long long*)(cBh + k * BPad + cb);
            }
            #pragma unroll
            for (int i = 0; i < 4; i++)
                #pragma unroll
                for (int g = 0; g < 3; g++) {
                    fma2(ai2[i][g], rhc2[i], wi2[g]);
                    fma2(ah2[i][g], rxp2[i], wh2[g]);
                }
        }

        if (t + 1 < nT) {
            int nb = (t + 1) & 1;
            #pragma unroll
            for (int i = 0; i < 6; i++) {
                int c = bc + i * 64;
                Bi[nb][bk * BPad + c] = pbi[i];
                Bh[nb][bk * BPad + c] = pbh[i];
            }
            if (amat) Axp[nb][ak * APad + ar] = pav;
            else      Ahc[nb][ak * APad + ar] = pav;
            __syncthreads();
        }
    }

    float bi_[3][2], bh_[3][2];
    #pragma unroll
    for (int g = 0; g < 3; g++)
        #pragma unroll
        for (int q = 0; q < 2; q++) {
            bi_[g][q] = bih[g * 128 + tx * 2 + q];
            bh_[g][q] = bhh[g * 128 + tx * 2 + q];
        }

    float ls[2], ls2[2];
    ls[0] = ls[1] = ls2[0] = ls2[1] = 0.f;

    #pragma unroll
    for (int i = 0; i < 4; i++) {
        int row = bm + ty * 4 + i;
        if (row >= n) break;
        float2 aiv[3], ahv[3];
        #pragma unroll
        for (int g = 0; g < 3; g++) { aiv[g] = unpk2(ai2[i][g]); ahv[g] = unpk2(ah2[i][g]); }
        #pragma unroll
        for (int q = 0; q < 2; q++) {
            int c = tx * 2 + q;
            float a0 = q ? aiv[0].y : aiv[0].x, h0 = q ? ahv[0].y : ahv[0].x;
            float a1 = q ? aiv[1].y : aiv[1].x, h1 = q ? ahv[1].y : ahv[1].x;
            float a2 = q ? aiv[2].y : aiv[2].x, h2 = q ? ahv[2].y : ahv[2].x;
            float gr = (a0 + bi_[0][q]) + (h0 + bh_[0][q]);
            float gz = (a1 + bi_[1][q]) + (h1 + bh_[1][q]);
            float r = 1.f / (1.f + expf(-gr));
            float z = 1.f / (1.f + expf(-gz));
            float nn = tanhf((a2 + bi_[2][q]) + r * (h2 + bh_[2][q]));
            float hprev = xprev[(size_t)row * 128 + c];
            float val = (1.f - z) * nn + z * hprev;
            if (LAYER == 1) {
                outH[(size_t)row * 128 + c] = fmaxf(val, 0.f);
            } else {
                val += g_pool[OFF_SK + (size_t)row * 128 + c];
                outH[(size_t)row * 128 + c] = val;
                ls[q] += val;
                ls2[q] += val * val;
            }
        }
    }

    if (LAYER == 2) {
        __syncthreads();
        float* red = Bi[0];
        red[(tx * 2 + 0) * 8 + ty] = ls[0];
        red[(tx * 2 + 1) * 8 + ty] = ls[1];
        float* red2 = Bh[0];
        red2[(tx * 2 + 0) * 8 + ty] = ls2[0];
        red2[(tx * 2 + 1) * 8 + ty] = ls2[1];
        __syncthreads();
        if (tid < 128) {
            float s = 0.f, s2 = 0.f;
            #pragma unroll
            for (int t = 0; t < 8; t++) { s += red[tid * 8 + t]; s2 += red2[tid * 8 + t]; }
            g_ps1[(size_t)blockIdx.x * CCH + tid] = s;
            g_ps2[(size_t)blockIdx.x * CCH + tid] = s2;
        }
    }
}

// ---------------------------------------------------------------------------
// CSR build
// ---------------------------------------------------------------------------
__global__ void k_prep(int n) {
    int i = blockIdx.x * blockDim.x + threadIdx.x;
    if (i < n) { g_deg[i] = 0; g_cursor[i] = 0; }
}
__global__ void k_count(const int* __restrict__ ei, int e) {
    int i = blockIdx.x * blockDim.x + threadIdx.x;
    if (i < e) atomicAdd(&g_deg[ei[e + i]], 1);
}
__global__ void k_scan_dinv(int n) {
    __shared__ int wsum[32];
    const int tid = threadIdx.x;
    const int lane = tid & 31, wid = tid >> 5;
    int base = 0;
    for (int t0 = 0; t0 < n; t0 += 1024) {
        int i = t0 + tid;
        int d = (i < n) ? g_deg[i] : 0;
        int v = d;
        #pragma unroll
        for (int o = 1; o < 32; o <<= 1) {
            int t = __shfl_up_sync(0xffffffffu, v, o);
            if (lane >= o) v += t;
        }
        if (lane == 31) wsum[wid] = v;
        __syncthreads();
        if (wid == 0) {
            int w = wsum[lane];
            #pragma unroll
            for (int o = 1; o < 32; o <<= 1) {
                int t = __shfl_up_sync(0xffffffffu, w, o);
                if (lane >= o) w += t;
            }
            wsum[lane] = w;
        }
        __syncthreads();
        int excl = (v - d) + (wid ? wsum[wid - 1] : 0);
        if (i < n) {
            g_rowptr[i] = base + excl;
            g_dinv[i] = rsqrtf((float)(d + 1));
        }
        base += wsum[31];
        __syncthreads();
    }
    if (tid == 0) g_rowptr[n] = base;
}
__global__ void k_place(const int* __restrict__ ei, int e) {
    int i = blockIdx.x * blockDim.x + threadIdx.x;
    if (i >= e) return;
    int s = ei[i];
    int d = ei[e + i];
    int p = g_rowptr[d] + atomicAdd(&g_cursor[d], 1);
    g_edge[p] = make_int2(s, __float_as_int(g_dinv[s] * g_dinv[d]));
}

// ---------------------------------------------------------------------------
// Gather (warp per node)
// ---------------------------------------------------------------------------
__global__ __launch_bounds__(256)
void k_gather(const float* __restrict__ h, const float* __restrict__ bias, int n) {
    int w = (blockIdx.x * blockDim.x + threadIdx.x) >> 5;
    int lane = threadIdx.x & 31;
    if (w >= n) return;
    int beg = g_rowptr[w], end = g_rowptr[w + 1];
    float di = g_dinv[w];
    float4 hv = *(const float4*)(h + (size_t)w * CCH + lane * 4);
    float sl = di * di;
    float ax = sl * hv.x, ay = sl * hv.y, az = sl * hv.z, aw = sl * hv.w;

    int j = beg;
    for (; j + 3 < end; j += 4) {
        int2 e0 = g_edge[j],     e1 = g_edge[j + 1];
        int2 e2 = g_edge[j + 2], e3 = g_edge[j + 3];
        float4 v0 = *(const float4*)(h + (size_t)e0.x * CCH + lane * 4);
        float4 v1 = *(const float4*)(h + (size_t)e1.x * CCH + lane * 4);
        float4 v2 = *(const float4*)(h + (size_t)e2.x * CCH + lane * 4);
        float4 v3 = *(const float4*)(h + (size_t)e3.x * CCH + lane * 4);
        float c0 = __int_as_float(e0.y), c1 = __int_as_float(e1.y);
        float c2 = __int_as_float(e2.y), c3 = __int_as_float(e3.y);
        ax = fmaf(c0, v0.x, ax); ay = fmaf(c0, v0.y, ay);
        az = fmaf(c0, v0.z, az); aw = fmaf(c0, v0.w, aw);
        ax = fmaf(c1, v1.x, ax); ay = fmaf(c1, v1.y, ay);
        az = fmaf(c1, v1.z, az); aw = fmaf(c1, v1.w, aw);
        ax = fmaf(c2, v2.x, ax); ay = fmaf(c2, v2.y, ay);
        az = fmaf(c2, v2.z, az); aw = fmaf(c2, v2.w, aw);
        ax = fmaf(c3, v3.x, ax); ay = fmaf(c3, v3.y, ay);
        az = fmaf(c3, v3.z, az); aw = fmaf(c3, v3.w, aw);
    }
    for (; j < end; j++) {
        int2 e0 = g_edge[j];
        float c0 = __int_as_float(e0.y);
        float4 v0 = *(const float4*)(h + (size_t)e0.x * CCH + lane * 4);
        ax = fmaf(c0, v0.x, ax); ay = fmaf(c0, v0.y, ay);
        az = fmaf(c0, v0.z, az); aw = fmaf(c0, v0.w, aw);
    }
    float b0 = bias[lane * 4 + 0], b1 = bias[lane * 4 + 1];
    float b2 = bias[lane * 4 + 2], b3 = bias[lane * 4 + 3];
    float4 o; o.x = ax + b0; o.y = ay + b1; o.z = az + b2; o.w = aw + b3;
    *(float4*)(g_pool + OFF_HC + (size_t)w * CCH + lane * 4) = o;
}

// ---------------------------------------------------------------------------
// BN
// ---------------------------------------------------------------------------
__global__ void k_bnstats(int nblocks, int n) {
    int c = threadIdx.x;
    float s = 0.f, comp = 0.f, s2 = 0.f, comp2 = 0.f;
    for (int b = 0; b < nblocks; b++) {
        float y = g_ps1[(size_t)b * CCH + c] - comp;
        float t = s + y; comp = (t - s) - y; s = t;
        float y2 = g_ps2[(size_t)b * CCH + c] - comp2;
        float t2 = s2 + y2; comp2 = (t2 - s2) - y2; s2 = t2;
    }
    float invn = 1.f / (float)n;
    float mean = s * invn;
    float var = s2 * invn - mean * mean;
    g_mean[c] = mean;
    g_scale[c] = rsqrtf(var + EPS_BN);
}
__global__ void k_bnapply(float* __restrict__ out2, int n) {
    int idx = blockIdx.x * blockDim.x + threadIdx.x;
    if (idx >= n * CCH) return;
    int c = idx & 127;
    out2[idx] = (out2[idx] - g_mean[c]) * g_scale[c];
}

// ---------------------------------------------------------------------------
// Launch — CSR + skip on side stream.
// ---------------------------------------------------------------------------
extern "C" void kernel_launch(void* const* d_in, const int* in_sizes, int n_in,
                              void* d_out, int out_size) {
    const float* nf    = (const float*)d_in[0];
    const int*   ei    = (const int*)d_in[1];
    const float* xp1   = (const float*)d_in[2];
    const float* xp2   = (const float*)d_in[3];
    const float* ts    = (const float*)d_in[4];
    const float* freq  = (const float*)d_in[5];
    const float* phase = (const float*)d_in[6];
    const float* mW    = (const float*)d_in[7];
    const float* mb    = (const float*)d_in[8];
    const float* W1    = (const float*)d_in[9];
    const float* b1    = (const float*)d_in[10];
    const float* g1Wih = (const float*)d_in[11];
    const float* g1Whh = (const float*)d_in[12];
    const float* g1bih = (const float*)d_in[13];
    const float* g1bhh = (const float*)d_in[14];
    const float* W2    = (const float*)d_in[15];
    const float* b2    = (const float*)d_in[16];
    const float* g2Wih = (const float*)d_in[17];
    const float* g2Whh = (const float*)d_in[18];
    const float* g2bih = (const float*)d_in[19];
    const float* g2bhh = (const float*)d_in[20];
    const float* skW   = (const float*)d_in[21];
    const float* skb   = (const float*)d_in[22];

    float* out = (float*)d_out;

    const int n = in_sizes[0] / CCH;
    const int e = in_sizes[1] / 2;
    const int nc = n * CCH;

    float* H1 = out;
    float* H2 = out + nc;

    const int T = 256;
    dim3 gN(ceildiv(n, T));
    dim3 gE(ceildiv(e, T));
    dim3 gNC(ceildiv(nc, T));
    dim3 gGat(ceildiv(n * 32, T));
    dim3 gM(ceildiv(n, BM));
    int nbg = ceildiv(n, 32);

    static cudaStream_t s2 = nullptr;
    static cudaEvent_t evFork = nullptr, evJoin = nullptr, evMerge = nullptr, evSkip = nullptr;
    if (!s2) {
        cudaStreamCreateWithFlags(&s2, cudaStreamNonBlocking);
        cudaEventCreateWithFlags(&evFork, cudaEventDisableTiming);
        cudaEventCreateWithFlags(&evJoin, cudaEventDisableTiming);
        cudaEventCreateWithFlags(&evMerge, cudaEventDisableTiming);
        cudaEventCreateWithFlags(&evSkip, cudaEventDisableTiming);
    }

    // fork
    cudaEventRecord(evFork, 0);
    cudaStreamWaitEvent(s2, evFork, 0);

    // s2: CSR chain, then skip GEMM (after merge)
    k_prep     <<<gN, T, 0, s2>>>(n);
    k_count    <<<gE, T, 0, s2>>>(ei, e);
    k_scan_dinv<<<1, 1024, 0, s2>>>(n);
    k_place    <<<gE, T, 0, s2>>>(ei, e);
    cudaEventRecord(evJoin, s2);

    // main: merge, then w1
    gemm_merge<<<gM, 256>>>(nf, ts, freq, phase, mW, mb, n);
    cudaEventRecord(evMerge, 0);
    gemm_w1<<<gM, 256>>>(W1, H2, n);

    // s2: skip after merge done
    cudaStreamWaitEvent(s2, evMerge, 0);
    gemm_skip<<<gM, 256, 0, s2>>>(skW, skb, n);
    cudaEventRecord(evSkip, s2);

    // join CSR before gather1
    cudaStreamWaitEvent(0, evJoin, 0);

    // ---- layer 1 ----
    k_gather<<<gGat, T>>>(H2, b1, n);
    gru_fused<1><<<nbg, 512>>>(g1Wih, g1Whh, g1bih, g1bhh, xp1, H1, n);

    // ---- layer 2 ----
    gemm_w2<<<gM, 256>>>(H1, W2, H2, n);
    k_gather<<<gGat, T>>>(H2, b2, n);
    cudaStreamWaitEvent(0, evSkip, 0);
    gru_fused<2><<<nbg, 512>>>(g2Wih, g2Whh, g2bih, g2bhh, xp2, H2, n);

    // batchnorm
    k_bnstats<<<1, 128>>>(nbg, n);
    k_bnapply<<<gNC, T>>>(H2, n);
}